// round 2
// baseline (speedup 1.0000x reference)
#include <cuda_runtime.h>
#include <math.h>

#define D 128
#define T 64
#define BATCH 512
#define EPS 1e-5f
#define FULLMASK 0xffffffffu

// -------- scratch (device globals; no allocation allowed) --------
__device__ float g_v[D * D];                 // row-normalized W
__device__ float g_rT[(T - 1) * BATCH * D];  // returns transposed: [t][b][d]
__device__ float g_h0T[BATCH * D];           // input[:,0,:] transposed: [b][d]
__device__ float g_outT[T * BATCH * D];      // output transposed: [t][b][d]

// -------- v = W / max(||W_row||, 1e-12) --------
__global__ void prep_v_kernel(const float* __restrict__ W) {
    int i = threadIdx.x;  // row
    float ss = 0.f;
#pragma unroll 8
    for (int j = 0; j < D; j++) {
        float w = W[i * D + j];
        ss += w * w;
    }
    float nrm = fmaxf(sqrtf(ss), 1e-12f);
    for (int j = 0; j < D; j++) g_v[i * D + j] = W[i * D + j] / nrm;
}

// -------- transpose returns (and input t=0 slice) into [t][b][d] --------
// grid: (BATCH/32, D/32, T). z < T-1: returns slice t=z. z == T-1: input slice t=0.
__global__ void transpose_in_kernel(const float* __restrict__ inp,
                                    const float* __restrict__ ret) {
    __shared__ float tile[32][33];
    int z = blockIdx.z;
    int b0 = blockIdx.x * 32, d0 = blockIdx.y * 32;
    int tx = threadIdx.x, ty = threadIdx.y;  // (32, 8)
    const float* srcbase;
    float* dst;
    if (z < T - 1) {
        srcbase = ret + (size_t)z * BATCH;        // element (d,b) at d*T*B + b
        dst = g_rT + (size_t)z * BATCH * D;
    } else {
        srcbase = inp;                            // input[:,0,:]
        dst = g_h0T;
    }
#pragma unroll
    for (int i = 0; i < 32; i += 8)
        tile[ty + i][tx] = srcbase[(size_t)(d0 + ty + i) * T * BATCH + (b0 + tx)];
    __syncthreads();
#pragma unroll
    for (int i = 0; i < 32; i += 8)
        dst[(size_t)(b0 + ty + i) * D + (d0 + tx)] = tile[tx][ty + i];
}

// -------- transpose outT [t][b][d] -> out (D,T,B); also emit h_last --------
__global__ void transpose_out_kernel(float* __restrict__ out) {
    __shared__ float tile[32][33];
    int t = blockIdx.z;
    int b0 = blockIdx.x * 32, d0 = blockIdx.y * 32;
    int tx = threadIdx.x, ty = threadIdx.y;
    const float* src = g_outT + (size_t)t * BATCH * D;  // (b,d), row stride D
#pragma unroll
    for (int i = 0; i < 32; i += 8)
        tile[ty + i][tx] = src[(size_t)(b0 + ty + i) * D + (d0 + tx)];
    __syncthreads();
#pragma unroll
    for (int i = 0; i < 32; i += 8) {
        float val = tile[tx][ty + i];
        int d = d0 + ty + i;
        int b = b0 + tx;
        out[(size_t)d * T * BATCH + (size_t)t * BATCH + b] = val;
        if (t == T - 1)  // h_last = output[:, T-1, :]
            out[(size_t)D * T * BATCH + (size_t)d * BATCH + b] = val;
    }
}

// -------- main recurrence: 1 warp per batch column, thread owns 4 dims --------
__global__ void __launch_bounds__(128) rnn_main_kernel(const float* __restrict__ tgt_g,
                                                       const float* __restrict__ b_g) {
    extern __shared__ float smem[];
    float* sv = smem;            // v padded: [128][129]
    float* xb = smem + D * 129;  // per-warp x buffer: [4][128]

    int tid = threadIdx.x, lane = tid & 31, warp = tid >> 5;

    // load v into padded smem (conflict-free column access later)
    for (int idx = tid; idx < D * D; idx += 128)
        sv[(idx >> 7) * 129 + (idx & 127)] = g_v[idx];
    __syncthreads();

    int col = blockIdx.x * 4 + warp;  // grid=128 -> col in [0,512)
    float* xw = xb + warp * D;

    float h4[4], tgt4[4], ab4[4], vd4[4], bp4[4], bn4[4];
#pragma unroll
    for (int q = 0; q < 4; q++) {
        int d = lane + 32 * q;
        tgt4[q] = tgt_g[d];
        ab4[q] = fabsf(b_g[d]);
        vd4[q] = sv[d * 129 + d];
        bp4[q] = ab4[q] + EPS;
        bn4[q] = -ab4[q] - EPS;
        float h0 = g_h0T[(size_t)col * D + d];
        h4[q] = h0;
        g_outT[(size_t)col * D + d] = h0;  // t = 0 slice
    }

    for (int t = 1; t < T; t++) {
        // ---- adj = h*(1+r) / (1 + sum(h*r)) ----
        float r4[4], adj4[4], x4[4];
        float acc = 0.f;
#pragma unroll
        for (int q = 0; q < 4; q++) {
            int d = lane + 32 * q;
            r4[q] = g_rT[((size_t)(t - 1) * BATCH + col) * D + d];
            acc += h4[q] * r4[q];
        }
#pragma unroll
        for (int o = 16; o; o >>= 1) acc += __shfl_xor_sync(FULLMASK, acc, o);
        float denom = 1.0f + acc;
#pragma unroll
        for (int q = 0; q < 4; q++) {
            adj4[q] = h4[q] * (1.0f + r4[q]) / denom;
            x4[q] = adj4[q] - tgt4[q];
            xw[lane + 32 * q] = x4[q];
        }
        __syncwarp();

        // ---- s = v @ (adj - pi_bar) ----
        float s4[4] = {0.f, 0.f, 0.f, 0.f};
#pragma unroll 4
        for (int i = 0; i < D; i++) {
            float xi = xw[i];
#pragma unroll
            for (int q = 0; q < 4; q++)
                s4[q] = fmaf(sv[(lane + 32 * q) * 129 + i], xi, s4[q]);
        }
        __syncwarp();  // xw reads done before next-iteration writes

        // ---- delta + feas0 ----
        float del4[4];
        bool loc = true;
#pragma unroll
        for (int q = 0; q < 4; q++) {
            float s = s4[q];
            float num = 0.f;
            if (s > ab4[q]) num = ab4[q] - s;
            else if (s < -ab4[q]) num = -ab4[q] - s;
            del4[q] = (num != 0.f) ? num / vd4[q] : 0.f;
            loc = loc && (s < bp4[q]) && (s > bn4[q]);
        }
        bool feas0 = __all_sync(FULLMASK, loc);
        bool judge = feas0;

        // ---- judge: any single-coordinate fix feasible? ----
        if (!judge) {
#pragma unroll
            for (int sl = 0; sl < 4; sl++) {
                if (judge) continue;
                float cand = del4[sl];
                for (int ln = 0; ln < 32; ln++) {
                    float di = __shfl_sync(FULLMASK, cand, ln);
                    if (di == 0.f) continue;  // uniform: contributes feas0 (=false)
                    int i = sl * 32 + ln;
                    bool ok = true;
#pragma unroll
                    for (int q = 0; q < 4; q++) {
                        float sn = fmaf(sv[(lane + 32 * q) * 129 + i], di, s4[q]);
                        ok = ok && (sn < bp4[q]) && (sn > bn4[q]);
                    }
                    if (__all_sync(FULLMASK, ok)) { judge = true; break; }
                }
            }
        }

        float hres4[4];
        if (judge) {
            if (feas0) {
                // sweep is a no-op: all d_j = 0
#pragma unroll
                for (int q = 0; q < 4; q++) hres4[q] = adj4[q];
            } else {
                // ---- Gauss-Seidel sweep (forward substitution via rank-1 updates) ----
                float ssl[4], ht4[4];
#pragma unroll
                for (int q = 0; q < 4; q++) { ssl[q] = s4[q]; ht4[q] = adj4[q]; }
                bool done = false;
#pragma unroll
                for (int sl = 0; sl < 4; sl++) {
                    if (done) continue;
                    for (int ln = 0; ln < 32; ln++) {
                        float s = ssl[sl];
                        float num = 0.f;
                        if (s > ab4[sl]) num = ab4[sl] - s;
                        else if (s < -ab4[sl]) num = -ab4[sl] - s;
                        float cand = (num != 0.f) ? num / vd4[sl] : 0.f;
                        float dj = __shfl_sync(FULLMASK, cand, ln);
                        if (dj != 0.f) {
                            int j = sl * 32 + ln;
#pragma unroll
                            for (int q = 0; q < 4; q++)
                                ssl[q] = fmaf(sv[(lane + 32 * q) * 129 + j], dj, ssl[q]);
                            if (lane == ln) ht4[sl] += dj;
                        }
                    }
                    // early exit: if everything is inside bounds, no future update fires
                    bool quiet = true;
#pragma unroll
                    for (int q = 0; q < 4; q++)
                        quiet = quiet && (ssl[q] <= ab4[q]) && (ssl[q] >= -ab4[q]);
                    if (__all_sync(FULLMASK, quiet)) done = true;
                }
#pragma unroll
                for (int q = 0; q < 4; q++) hres4[q] = ht4[q];
            }
        } else {
            // ---- bisection, collapsed to scalar alpha on segment pi + a*(h-pi) ----
            // feasible(a) <=> for all k: |a*s_k| <= |b_k|+EPS  <=> a <= min_k bp_k/|s_k|
            float am = __int_as_float(0x7f800000);  // +inf
#pragma unroll
            for (int q = 0; q < 4; q++) {
                float as = fabsf(s4[q]);
                float lim = (as > 0.f) ? bp4[q] / as : __int_as_float(0x7f800000);
                am = fminf(am, lim);
            }
#pragma unroll
            for (int o = 16; o; o >>= 1)
                am = fminf(am, __shfl_xor_sync(FULLMASK, am, o));
            float ain = 0.f, aout = 1.f, amid = 0.5f;
#pragma unroll
            for (int it = 0; it < 10; it++) {
                amid = ain + (aout - ain) * 0.5f;
                if (amid <= am) ain = amid; else aout = amid;
            }
#pragma unroll
            for (int q = 0; q < 4; q++)
                hres4[q] = fmaf(amid, x4[q], tgt4[q]);
        }

#pragma unroll
        for (int q = 0; q < 4; q++) {
            h4[q] = hres4[q];
            g_outT[((size_t)t * BATCH + col) * D + (lane + 32 * q)] = hres4[q];
        }
    }
}

extern "C" void kernel_launch(void* const* d_in, const int* in_sizes, int n_in,
                              void* d_out, int out_size) {
    const float* inp = (const float*)d_in[0];   // (D,T,B)
    const float* tgt = (const float*)d_in[1];   // (D,)
    const float* ret = (const float*)d_in[2];   // (D,T,B)
    // d_in[3] = hidden (unused by reference)
    const float* W = (const float*)d_in[4];     // (D,D)
    const float* bb = (const float*)d_in[5];    // (D,)
    float* out = (float*)d_out;                 // D*T*B output + D*B h_last

    prep_v_kernel<<<1, 128>>>(W);

    dim3 tb(32, 8);
    transpose_in_kernel<<<dim3(BATCH / 32, D / 32, T), tb>>>(inp, ret);

    size_t smem_bytes = (size_t)(D * 129 + 4 * D) * sizeof(float);
    cudaFuncSetAttribute(rnn_main_kernel,
                         cudaFuncAttributeMaxDynamicSharedMemorySize,
                         (int)smem_bytes);
    rnn_main_kernel<<<128, 128, smem_bytes>>>(tgt, bb);

    transpose_out_kernel<<<dim3(BATCH / 32, D / 32, T), tb>>>(out);
}

// round 3
// speedup vs baseline: 2.1174x; 2.1174x over previous
#include <cuda_runtime.h>
#include <math.h>

#define D 128
#define T 64
#define BATCH 512
#define EPS 1e-5f
#define FULLMASK 0xffffffffu

// -------- scratch (device globals; no allocation allowed) --------
__device__ float g_v[D * D];                 // row-normalized W
__device__ float g_rT[(T - 1) * BATCH * D];  // returns transposed: [t][b][d]
__device__ float g_h0T[BATCH * D];           // input[:,0,:] transposed: [b][d]
__device__ float g_outT[T * BATCH * D];      // output transposed: [t][b][d]

// -------- v = W / max(||W_row||, 1e-12) --------
__global__ void prep_v_kernel(const float* __restrict__ W) {
    int i = threadIdx.x;  // row
    float ss = 0.f;
#pragma unroll 8
    for (int j = 0; j < D; j++) {
        float w = W[i * D + j];
        ss += w * w;
    }
    float nrm = fmaxf(sqrtf(ss), 1e-12f);
    for (int j = 0; j < D; j++) g_v[i * D + j] = W[i * D + j] / nrm;
}

// -------- transpose returns (and input t=0 slice) into [t][b][d] --------
// grid: (BATCH/32, D/32, T). z < T-1: returns slice t=z. z == T-1: input slice t=0.
__global__ void transpose_in_kernel(const float* __restrict__ inp,
                                    const float* __restrict__ ret) {
    __shared__ float tile[32][33];
    int z = blockIdx.z;
    int b0 = blockIdx.x * 32, d0 = blockIdx.y * 32;
    int tx = threadIdx.x, ty = threadIdx.y;  // (32, 8)
    const float* srcbase;
    float* dst;
    if (z < T - 1) {
        srcbase = ret + (size_t)z * BATCH;        // element (d,b) at d*T*B + b
        dst = g_rT + (size_t)z * BATCH * D;
    } else {
        srcbase = inp;                            // input[:,0,:]
        dst = g_h0T;
    }
#pragma unroll
    for (int i = 0; i < 32; i += 8)
        tile[ty + i][tx] = srcbase[(size_t)(d0 + ty + i) * T * BATCH + (b0 + tx)];
    __syncthreads();
#pragma unroll
    for (int i = 0; i < 32; i += 8)
        dst[(size_t)(b0 + ty + i) * D + (d0 + tx)] = tile[tx][ty + i];
}

// -------- transpose outT [t][b][d] -> out (D,T,B); also emit h_last --------
__global__ void transpose_out_kernel(float* __restrict__ out) {
    __shared__ float tile[32][33];
    int t = blockIdx.z;
    int b0 = blockIdx.x * 32, d0 = blockIdx.y * 32;
    int tx = threadIdx.x, ty = threadIdx.y;
    const float* src = g_outT + (size_t)t * BATCH * D;  // (b,d), row stride D
#pragma unroll
    for (int i = 0; i < 32; i += 8)
        tile[ty + i][tx] = src[(size_t)(b0 + ty + i) * D + (d0 + tx)];
    __syncthreads();
#pragma unroll
    for (int i = 0; i < 32; i += 8) {
        float val = tile[tx][ty + i];
        int d = d0 + ty + i;
        int b = b0 + tx;
        out[(size_t)d * T * BATCH + (size_t)t * BATCH + b] = val;
        if (t == T - 1)  // h_last = output[:, T-1, :]
            out[(size_t)D * T * BATCH + (size_t)d * BATCH + b] = val;
    }
}

// -------- main recurrence: 1 warp per batch column, thread owns 4 dims --------
__global__ void __launch_bounds__(128) rnn_main_kernel(const float* __restrict__ tgt_g,
                                                       const float* __restrict__ b_g) {
    extern __shared__ float smem[];
    float* sv = smem;            // v padded: [128][129]
    float* xb = smem + D * 129;  // per-warp x buffer: [4][128]

    int tid = threadIdx.x, lane = tid & 31, warp = tid >> 5;

    // load v into padded smem (conflict-free column access later)
    for (int idx = tid; idx < D * D; idx += 128)
        sv[(idx >> 7) * 129 + (idx & 127)] = g_v[idx];
    __syncthreads();

    int col = blockIdx.x * 4 + warp;  // grid=128 -> col in [0,512)
    float* xw = xb + warp * D;

    float h4[4], tgt4[4], ab4[4], rvd4[4], bp4[4], bn4[4];
#pragma unroll
    for (int q = 0; q < 4; q++) {
        int d = lane + 32 * q;
        tgt4[q] = tgt_g[d];
        ab4[q] = fabsf(b_g[d]);
        rvd4[q] = 1.0f / sv[d * 129 + d];  // reciprocal of diagonal (off hot chain)
        bp4[q] = ab4[q] + EPS;
        bn4[q] = -ab4[q] - EPS;
        float h0 = g_h0T[(size_t)col * D + d];
        h4[q] = h0;
        g_outT[(size_t)col * D + d] = h0;  // t = 0 slice
    }

    for (int t = 1; t < T; t++) {
        // ---- adj = h*(1+r) / (1 + sum(h*r)) ----
        float r4[4], adj4[4], x4[4];
        float acc = 0.f;
#pragma unroll
        for (int q = 0; q < 4; q++) {
            int d = lane + 32 * q;
            r4[q] = g_rT[((size_t)(t - 1) * BATCH + col) * D + d];
            acc += h4[q] * r4[q];
        }
#pragma unroll
        for (int o = 16; o; o >>= 1) acc += __shfl_xor_sync(FULLMASK, acc, o);
        float denom = 1.0f + acc;
#pragma unroll
        for (int q = 0; q < 4; q++) {
            adj4[q] = h4[q] * (1.0f + r4[q]) / denom;
            x4[q] = adj4[q] - tgt4[q];
            xw[lane + 32 * q] = x4[q];
        }
        __syncwarp();

        // ---- s = v @ (adj - pi_bar) ----
        float s4[4] = {0.f, 0.f, 0.f, 0.f};
#pragma unroll 4
        for (int i = 0; i < D; i++) {
            float xi = xw[i];
#pragma unroll
            for (int q = 0; q < 4; q++)
                s4[q] = fmaf(sv[(lane + 32 * q) * 129 + i], xi, s4[q]);
        }
        __syncwarp();  // xw reads done before next-iteration writes

        // ---- delta + feas0 ----
        float del4[4];
        bool loc = true;
#pragma unroll
        for (int q = 0; q < 4; q++) {
            float s = s4[q];
            float num = 0.f;
            if (s > ab4[q]) num = ab4[q] - s;
            else if (s < -ab4[q]) num = -ab4[q] - s;
            del4[q] = num * rvd4[q];
            loc = loc && (s < bp4[q]) && (s > bn4[q]);
        }
        bool feas0 = __all_sync(FULLMASK, loc);
        bool judge = feas0;

        // ---- judge: any single-coordinate fix feasible? (ballot over nonzero deltas)
        if (!judge) {
#pragma unroll
            for (int sl = 0; sl < 4; sl++) {
                if (judge) continue;
                unsigned mask = __ballot_sync(FULLMASK, del4[sl] != 0.f);
                while (mask) {
                    int ln = __ffs(mask) - 1;
                    mask &= mask - 1;
                    float di = __shfl_sync(FULLMASK, del4[sl], ln);
                    int i = sl * 32 + ln;
                    bool ok = true;
#pragma unroll
                    for (int q = 0; q < 4; q++) {
                        float sn = fmaf(sv[(lane + 32 * q) * 129 + i], di, s4[q]);
                        ok = ok && (sn < bp4[q]) && (sn > bn4[q]);
                    }
                    if (__all_sync(FULLMASK, ok)) { judge = true; break; }
                }
            }
        }

        float hres4[4];
        if (judge) {
            if (feas0) {
                // sweep is a no-op: all d_j = 0
#pragma unroll
                for (int q = 0; q < 4; q++) hres4[q] = adj4[q];
            } else {
                // ---- Gauss-Seidel sweep: ballot-driven, skips non-firing coords.
                // Exact vs. the reference's strictly-increasing single pass:
                // skipped coords are evaluated (via ballot) against the identical
                // state the reference would see when reaching them.
                float ssl[4], ht4[4];
#pragma unroll
                for (int q = 0; q < 4; q++) { ssl[q] = s4[q]; ht4[q] = adj4[q]; }
#pragma unroll
                for (int sl = 0; sl < 4; sl++) {
                    unsigned eligible = FULLMASK;
                    while (true) {
                        float s = ssl[sl];
                        float num = 0.f;
                        if (s > ab4[sl]) num = ab4[sl] - s;
                        else if (s < -ab4[sl]) num = -ab4[sl] - s;
                        unsigned mask = __ballot_sync(FULLMASK, num != 0.f) & eligible;
                        if (!mask) break;
                        int ln = __ffs(mask) - 1;
                        float cand = num * rvd4[sl];
                        float dj = __shfl_sync(FULLMASK, cand, ln);
                        int j = sl * 32 + ln;
#pragma unroll
                        for (int q = 0; q < 4; q++)
                            ssl[q] = fmaf(sv[(lane + 32 * q) * 129 + j], dj, ssl[q]);
                        if (lane == ln) ht4[sl] += dj;
                        eligible = (ln == 31) ? 0u : (FULLMASK << (ln + 1));
                    }
                }
#pragma unroll
                for (int q = 0; q < 4; q++) hres4[q] = ht4[q];
            }
        } else {
            // ---- bisection, collapsed to scalar alpha on segment pi + a*(h-pi) ----
            // feasible(a) <=> for all k: |a*s_k| <= |b_k|+EPS  <=> a <= min_k bp_k/|s_k|
            float am = __int_as_float(0x7f800000);  // +inf
#pragma unroll
            for (int q = 0; q < 4; q++) {
                float as = fabsf(s4[q]);
                float lim = (as > 0.f) ? bp4[q] / as : __int_as_float(0x7f800000);
                am = fminf(am, lim);
            }
#pragma unroll
            for (int o = 16; o; o >>= 1)
                am = fminf(am, __shfl_xor_sync(FULLMASK, am, o));
            float ain = 0.f, aout = 1.f, amid = 0.5f;
#pragma unroll
            for (int it = 0; it < 10; it++) {
                amid = ain + (aout - ain) * 0.5f;
                if (amid <= am) ain = amid; else aout = amid;
            }
#pragma unroll
            for (int q = 0; q < 4; q++)
                hres4[q] = fmaf(amid, x4[q], tgt4[q]);
        }

#pragma unroll
        for (int q = 0; q < 4; q++) {
            h4[q] = hres4[q];
            g_outT[((size_t)t * BATCH + col) * D + (lane + 32 * q)] = hres4[q];
        }
    }
}

extern "C" void kernel_launch(void* const* d_in, const int* in_sizes, int n_in,
                              void* d_out, int out_size) {
    const float* inp = (const float*)d_in[0];   // (D,T,B)
    const float* tgt = (const float*)d_in[1];   // (D,)
    const float* ret = (const float*)d_in[2];   // (D,T,B)
    // d_in[3] = hidden (unused by reference)
    const float* W = (const float*)d_in[4];     // (D,D)
    const float* bb = (const float*)d_in[5];    // (D,)
    float* out = (float*)d_out;                 // D*T*B output + D*B h_last

    prep_v_kernel<<<1, 128>>>(W);

    dim3 tb(32, 8);
    transpose_in_kernel<<<dim3(BATCH / 32, D / 32, T), tb>>>(inp, ret);

    size_t smem_bytes = (size_t)(D * 129 + 4 * D) * sizeof(float);
    cudaFuncSetAttribute(rnn_main_kernel,
                         cudaFuncAttributeMaxDynamicSharedMemorySize,
                         (int)smem_bytes);
    rnn_main_kernel<<<128, 128, smem_bytes>>>(tgt, bb);

    transpose_out_kernel<<<dim3(BATCH / 32, D / 32, T), tb>>>(out);
}